// round 7
// baseline (speedup 1.0000x reference)
#include <cuda_runtime.h>
#include <cstdint>

// logits [16, 2048, 1] fp32, seq_len [16] i32, out [16, 2048, 2048] fp32.
#define BB 16
#define TT 2048
#define WPB 8                 // warps per block; one output row per warp
#define THREADS (WPB * 32)

// Write-bandwidth-floor kernel (268 MB output @ ~6.4 TB/s effective => ~42us).
//  - fully-masked blocks: immediate zero stream, no staging, no barrier.
//  - partially-valid blocks: masked-row warps fire their zero stores BEFORE
//    staging (no data dependence), then help stage and sync; valid warps
//    stage sigmoid(logits[b,:]) to smem, compute one row each in registers,
//    warp-shfl reduce, streaming float4 stores.
//
// Max-free softmax is exact: rel values in (0.0067, 0.9933) -> exp in (1, e),
// no overflow; masked entries exactly 0, matching the reference's fp32
// exp(-1e9 - max) == 0.
__global__ __launch_bounds__(THREADS, 3) void fused_kernel(
    const float* __restrict__ logits,
    const int* __restrict__ seq_len,
    float* __restrict__ out)
{
    __shared__ float s_scores[TT];

    const int b    = blockIdx.y;
    const int tid  = threadIdx.x;
    const int warp = tid >> 5;
    const int lane = tid & 31;
    const int L    = seq_len[b];
    const int row0 = blockIdx.x * WPB;

    // ---- fast path: whole block is masked rows -> pure zero stream ----
    if (row0 >= L) {
        const float4 z = make_float4(0.f, 0.f, 0.f, 0.f);
        float* oblk = out + ((size_t)b * TT + (size_t)row0) * TT;
        #pragma unroll
        for (int k = 0; k < 16; k++)
            __stcs(reinterpret_cast<float4*>(oblk) + k * THREADS + tid, z);
        return;
    }

    const int  i         = row0 + warp;            // this warp's row
    const bool row_valid = (i < L);
    float* orow = out + ((size_t)b * TT + (size_t)i) * TT;

    // masked-row warps: zeros have no dependence on staging -> store FIRST,
    // so the store queue is fed while valid warps do MUFU work.
    if (!row_valid) {
        const float4 z = make_float4(0.f, 0.f, 0.f, 0.f);
        #pragma unroll
        for (int k = 0; k < 16; k++)
            __stcs(reinterpret_cast<float4*>(orow) + k * 32 + lane, z);
    }

    // ---- stage sigmoid(logits[b,:]) into smem (all threads, coalesced) ----
    {
        const float4* src = reinterpret_cast<const float4*>(logits + b * TT);
        #pragma unroll
        for (int k = 0; k < (TT / 4) / THREADS; k++) {
            const float4 x = src[tid + k * THREADS];
            float4 s;
            s.x = __fdividef(1.0f, 1.0f + __expf(-x.x));
            s.y = __fdividef(1.0f, 1.0f + __expf(-x.y));
            s.z = __fdividef(1.0f, 1.0f + __expf(-x.z));
            s.w = __fdividef(1.0f, 1.0f + __expf(-x.w));
            reinterpret_cast<float4*>(s_scores)[tid + k * THREADS] = s;
        }
    }
    __syncthreads();   // the ONLY block barrier

    if (!row_valid) return;

    const float s_i = s_scores[i];
    float e[64];
    float psum = 0.f;

    // chunk k covers j in [k*128, k*128+128) across the warp (warp-uniform bounds)
    #pragma unroll
    for (int k = 0; k < 16; k++) {
        const int fidx  = k * 32 + lane;     // float4 index
        const int jbase = fidx * 4;
        if ((k + 1) * 128 <= L) {
            // fully valid chunk: no predication
            const float4 sv = reinterpret_cast<const float4*>(s_scores)[fidx];
            const float sj[4] = {sv.x, sv.y, sv.z, sv.w};
            #pragma unroll
            for (int q = 0; q < 4; q++) {
                const float x   = fmaf(-10.0f, fabsf(s_i - sj[q]), 5.0f);
                const float sig = __fdividef(1.0f, 1.0f + __expf(-x));
                const float ev  = __expf(sig);
                e[k * 4 + q] = ev;
                psum += ev;
            }
        } else if (k * 128 >= L) {
            // fully invalid chunk: skip all math
            #pragma unroll
            for (int q = 0; q < 4; q++) e[k * 4 + q] = 0.f;
        } else {
            // straddling chunk (at most one per row): per-element predication
            #pragma unroll
            for (int q = 0; q < 4; q++) {
                const int j = jbase + q;
                float ev = 0.f;
                if (j < L) {
                    const float sj  = s_scores[j];
                    const float x   = fmaf(-10.0f, fabsf(s_i - sj), 5.0f);
                    const float sig = __fdividef(1.0f, 1.0f + __expf(-x));
                    ev = __expf(sig);
                }
                e[k * 4 + q] = ev;
                psum += ev;
            }
        }
    }

    // warp-local butterfly reduction -> every lane has the row sum
    #pragma unroll
    for (int off = 16; off > 0; off >>= 1)
        psum += __shfl_xor_sync(0xFFFFFFFFu, psum, off);
    const float inv = __fdividef(1.0f, psum);

    // normalized streaming stores (float4, coalesced per chunk)
    #pragma unroll
    for (int k = 0; k < 16; k++) {
        const float4 v = make_float4(e[k * 4 + 0] * inv, e[k * 4 + 1] * inv,
                                     e[k * 4 + 2] * inv, e[k * 4 + 3] * inv);
        __stcs(reinterpret_cast<float4*>(orow) + k * 32 + lane, v);
    }
}

extern "C" void kernel_launch(void* const* d_in, const int* in_sizes, int n_in,
                              void* d_out, int out_size) {
    const float* logits  = (const float*)d_in[0];   // [16, 2048, 1] fp32
    const int*   seq_len = (const int*)d_in[1];     // [16] i32
    float*       out     = (float*)d_out;           // [16, 2048, 2048] fp32

    dim3 grid(TT / WPB, BB);
    fused_kernel<<<grid, THREADS>>>(logits, seq_len, out);
}